// round 3
// baseline (speedup 1.0000x reference)
#include <cuda_runtime.h>
#include <math.h>

// Problem constants
#define Bc  2
#define Sc  2048
#define Dc  1024
#define Hc  16
#define DKc 64
#define BSc (Bc*Sc)   // 4096
#define BHc (Bc*Hc)   // 32

// Scratch (static device globals; allocation inside kernel_launch is forbidden)
__device__ float g_q  [(size_t)BSc*Dc];
__device__ float g_k  [(size_t)BSc*Dc];
__device__ float g_v  [(size_t)BSc*Dc];
__device__ float g_ctx[(size_t)BSc*Dc];
__device__ float g_m  [(size_t)BHc*Sc];
__device__ float g_l  [(size_t)BHc*Sc];

// ---------------------------------------------------------------------------
// C[M,N] = A[M,K] @ W[N,K]^T + bias[N]   (both operands K-contiguous, "NT")
// 64x64 tile, KT=16, 256 threads, 4x4 register blocking.
// ---------------------------------------------------------------------------
__global__ void gemm_nt_bias(const float* __restrict__ A,
                             const float* __restrict__ W,
                             const float* __restrict__ bias,
                             float* __restrict__ C,
                             int M, int N, int K) {
    __shared__ float As[16][65];
    __shared__ float Ws[16][65];
    const int t  = threadIdx.x;
    const int tx = t & 15;
    const int ty = t >> 4;
    const int m0 = blockIdx.y * 64;
    const int n0 = blockIdx.x * 64;

    float acc[4][4];
    #pragma unroll
    for (int i = 0; i < 4; i++)
        #pragma unroll
        for (int j = 0; j < 4; j++) acc[i][j] = 0.f;

    for (int k0 = 0; k0 < K; k0 += 16) {
        #pragma unroll
        for (int i = 0; i < 4; i++) {
            int row = ty + i * 16;   // 0..63
            int col = tx;            // 0..15
            As[col][row] = A[(size_t)(m0 + row) * K + k0 + col];
            Ws[col][row] = W[(size_t)(n0 + row) * K + k0 + col];
        }
        __syncthreads();
        #pragma unroll
        for (int kk = 0; kk < 16; kk++) {
            float a[4], b[4];
            #pragma unroll
            for (int i = 0; i < 4; i++) a[i] = As[kk][ty + i * 16];
            #pragma unroll
            for (int j = 0; j < 4; j++) b[j] = Ws[kk][tx + j * 16];
            #pragma unroll
            for (int i = 0; i < 4; i++)
                #pragma unroll
                for (int j = 0; j < 4; j++)
                    acc[i][j] += a[i] * b[j];
        }
        __syncthreads();
    }

    #pragma unroll
    for (int i = 0; i < 4; i++) {
        int m = m0 + ty + i * 16;
        #pragma unroll
        for (int j = 0; j < 4; j++) {
            int n = n0 + tx + j * 16;
            C[(size_t)m * N + n] = acc[i][j] + bias[n];
        }
    }
}

// ---------------------------------------------------------------------------
// Raw scores: attn[b,h,q,k] = (q_row . k_row) / 8   (written unnormalized)
// grid: (S/64 k-tiles, S/64 q-tiles, B*H)
// ---------------------------------------------------------------------------
__global__ void scores_kernel(const float* __restrict__ Q,
                              const float* __restrict__ Kp,
                              float* __restrict__ attn) {
    __shared__ float Qs[64][65];
    __shared__ float Ks[64][65];
    const int bh = blockIdx.z;
    const int b  = bh / Hc;
    const int h  = bh % Hc;
    const int q0 = blockIdx.y * 64;
    const int k0 = blockIdx.x * 64;
    const int t  = threadIdx.x;
    const int tx = t & 15;
    const int ty = t >> 4;

    for (int idx = t; idx < 64 * 64; idx += 256) {
        int r = idx >> 6, d = idx & 63;
        Qs[r][d] = Q[(size_t)(b * Sc + q0 + r) * Dc + h * DKc + d];
        Ks[r][d] = Kp[(size_t)(b * Sc + k0 + r) * Dc + h * DKc + d];
    }
    __syncthreads();

    float acc[4][4];
    #pragma unroll
    for (int i = 0; i < 4; i++)
        #pragma unroll
        for (int j = 0; j < 4; j++) acc[i][j] = 0.f;

    #pragma unroll 8
    for (int d = 0; d < 64; d++) {
        float a[4], bb[4];
        #pragma unroll
        for (int i = 0; i < 4; i++) a[i]  = Qs[ty + i * 16][d];
        #pragma unroll
        for (int j = 0; j < 4; j++) bb[j] = Ks[tx + j * 16][d];
        #pragma unroll
        for (int i = 0; i < 4; i++)
            #pragma unroll
            for (int j = 0; j < 4; j++)
                acc[i][j] += a[i] * bb[j];
    }

    const float sc = 0.125f;  // 1/sqrt(64)
    const size_t base = ((size_t)bh * Sc + q0) * Sc + k0;
    #pragma unroll
    for (int i = 0; i < 4; i++)
        #pragma unroll
        for (int j = 0; j < 4; j++)
            attn[base + (size_t)(ty + i * 16) * Sc + tx + j * 16] = acc[i][j] * sc;
}

// ---------------------------------------------------------------------------
// Row stats: m = max(row), l = sum(exp(row - m)).  One block per (b,h,q) row.
// ---------------------------------------------------------------------------
__global__ void rowstats_kernel(const float* __restrict__ attn) {
    const int row = blockIdx.x;            // 0 .. BH*S-1
    const size_t base = (size_t)row * Sc;
    const int t = threadIdx.x;

    float v[8];
    #pragma unroll
    for (int i = 0; i < 8; i++) v[i] = attn[base + t + i * 256];

    float mx = v[0];
    #pragma unroll
    for (int i = 1; i < 8; i++) mx = fmaxf(mx, v[i]);

    __shared__ float red[256];
    red[t] = mx;
    __syncthreads();
    for (int s = 128; s > 0; s >>= 1) {
        if (t < s) red[t] = fmaxf(red[t], red[t + s]);
        __syncthreads();
    }
    mx = red[0];
    __syncthreads();

    float sum = 0.f;
    #pragma unroll
    for (int i = 0; i < 8; i++) sum += expf(v[i] - mx);
    red[t] = sum;
    __syncthreads();
    for (int s = 128; s > 0; s >>= 1) {
        if (t < s) red[t] += red[t + s];
        __syncthreads();
    }
    if (t == 0) {
        g_m[row] = mx;
        g_l[row] = red[0];
    }
}

// ---------------------------------------------------------------------------
// Normalize attn in place + ctx = attn @ V.  grid: (S/64 q-tiles, B*H)
// ---------------------------------------------------------------------------
__global__ void av_kernel(float* __restrict__ attn,
                          const float* __restrict__ V,
                          float* __restrict__ ctx) {
    __shared__ float Ps[64][65];
    __shared__ float Vs[64][65];
    __shared__ float mrow[64];
    __shared__ float lrow[64];
    const int bh = blockIdx.y;
    const int b  = bh / Hc;
    const int h  = bh % Hc;
    const int q0 = blockIdx.x * 64;
    const int t  = threadIdx.x;
    const int tx = t & 15;
    const int ty = t >> 4;

    if (t < 64) {
        mrow[t] = g_m[(size_t)bh * Sc + q0 + t];
        lrow[t] = 1.0f / g_l[(size_t)bh * Sc + q0 + t];
    }
    __syncthreads();

    float acc[4][4];
    #pragma unroll
    for (int i = 0; i < 4; i++)
        #pragma unroll
        for (int j = 0; j < 4; j++) acc[i][j] = 0.f;

    for (int k0 = 0; k0 < Sc; k0 += 64) {
        for (int idx = t; idx < 64 * 64; idx += 256) {
            int r = idx >> 6, c = idx & 63;
            size_t a = ((size_t)bh * Sc + q0 + r) * Sc + k0 + c;
            float p = expf(attn[a] - mrow[r]) * lrow[r];
            attn[a] = p;
            Ps[r][c] = p;
            Vs[r][c] = V[(size_t)(b * Sc + k0 + r) * Dc + h * DKc + c];
        }
        __syncthreads();
        #pragma unroll 8
        for (int kk = 0; kk < 64; kk++) {
            float a[4], bb[4];
            #pragma unroll
            for (int i = 0; i < 4; i++) a[i]  = Ps[ty + i * 16][kk];
            #pragma unroll
            for (int j = 0; j < 4; j++) bb[j] = Vs[kk][tx + j * 16];
            #pragma unroll
            for (int i = 0; i < 4; i++)
                #pragma unroll
                for (int j = 0; j < 4; j++)
                    acc[i][j] += a[i] * bb[j];
        }
        __syncthreads();
    }

    #pragma unroll
    for (int i = 0; i < 4; i++) {
        int qg = q0 + ty + i * 16;
        #pragma unroll
        for (int j = 0; j < 4; j++)
            ctx[(size_t)(b * Sc + qg) * Dc + h * DKc + tx + j * 16] = acc[i][j];
    }
}

// ---------------------------------------------------------------------------
extern "C" void kernel_launch(void* const* d_in, const int* in_sizes, int n_in,
                              void* d_out, int out_size) {
    const float* x  = (const float*)d_in[0];
    const float* Wq = (const float*)d_in[1];
    const float* bq = (const float*)d_in[2];
    const float* Wk = (const float*)d_in[3];
    const float* bk = (const float*)d_in[4];
    const float* Wv = (const float*)d_in[5];
    const float* bv = (const float*)d_in[6];
    const float* Wo = (const float*)d_in[7];
    const float* bo = (const float*)d_in[8];

    float* out  = (float*)d_out;                       // [B,S,D]
    float* attn = out + (size_t)BSc * Dc;              // [B,H,S,S]

    float *q, *k, *v, *ctx;
    cudaGetSymbolAddress((void**)&q,   g_q);
    cudaGetSymbolAddress((void**)&k,   g_k);
    cudaGetSymbolAddress((void**)&v,   g_v);
    cudaGetSymbolAddress((void**)&ctx, g_ctx);

    dim3 gproj(Dc / 64, BSc / 64);
    gemm_nt_bias<<<gproj, 256>>>(x, Wq, bq, q, BSc, Dc, Dc);
    gemm_nt_bias<<<gproj, 256>>>(x, Wk, bk, k, BSc, Dc, Dc);
    gemm_nt_bias<<<gproj, 256>>>(x, Wv, bv, v, BSc, Dc, Dc);

    dim3 gsc(Sc / 64, Sc / 64, BHc);
    scores_kernel<<<gsc, 256>>>(q, k, attn);

    rowstats_kernel<<<BHc * Sc, 256>>>(attn);

    dim3 gav(Sc / 64, BHc);
    av_kernel<<<gav, 256>>>(attn, v, ctx);

    gemm_nt_bias<<<gproj, 256>>>(ctx, Wo, bo, out, BSc, Dc, Dc);
}

// round 5
// speedup vs baseline: 3.5986x; 3.5986x over previous
#include <cuda_runtime.h>
#include <math.h>
#include <stdint.h>

// Problem constants
#define Bc  2
#define Sc  2048
#define Dc  1024
#define Hc  16
#define DKc 64
#define BSc (Bc*Sc)   // 4096
#define BHc (Bc*Hc)   // 32

// Scratch (static device globals; allocation inside kernel_launch is forbidden)
__device__ float g_q  [(size_t)BSc*Dc];
__device__ float g_k  [(size_t)BSc*Dc];
__device__ float g_v  [(size_t)BSc*Dc];
__device__ float g_ctx[(size_t)BSc*Dc];
__device__ float g_m  [(size_t)BHc*Sc];
__device__ float g_l  [(size_t)BHc*Sc];

// ---------------------------------------------------------------------------
// helpers
// ---------------------------------------------------------------------------
__device__ __forceinline__ uint32_t f2tf(float x) {
    uint32_t r;
    asm("cvt.rna.tf32.f32 %0, %1;" : "=r"(r) : "f"(x));
    return r;
}

// D = A(16x8, row) * B(8x8, col) + C, tf32 inputs, fp32 accum
__device__ __forceinline__ void mma_tf32(float d[4], const uint32_t a[4],
                                         const uint32_t b[2], const float c[4]) {
    asm volatile(
        "mma.sync.aligned.m16n8k8.row.col.f32.tf32.tf32.f32 "
        "{%0,%1,%2,%3}, {%4,%5,%6,%7}, {%8,%9}, {%10,%11,%12,%13};\n"
        : "=f"(d[0]), "=f"(d[1]), "=f"(d[2]), "=f"(d[3])
        : "r"(a[0]), "r"(a[1]), "r"(a[2]), "r"(a[3]),
          "r"(b[0]), "r"(b[1]),
          "f"(c[0]), "f"(c[1]), "f"(c[2]), "f"(c[3]));
}

// ---------------------------------------------------------------------------
// C[M,N] = A[M,K] @ W[N,K]^T + bias[N]   (NT, both K-contiguous), tf32 MMA.
// Block tile 128x128, BK=32, 256 threads (8 warps: 2 M x 4 N, warp 64x32).
// ---------------------------------------------------------------------------
__global__ void gemm_tf32(const float* __restrict__ A,
                          const float* __restrict__ W,
                          const float* __restrict__ bias,
                          float* __restrict__ C,
                          int M, int N, int K) {
    __shared__ uint32_t As[128][36];
    __shared__ uint32_t Ws[128][36];
    const int t     = threadIdx.x;
    const int lane  = t & 31;
    const int warp  = t >> 5;
    const int g     = lane >> 2;   // group id 0..7
    const int tig   = lane & 3;    // thread-in-group 0..3
    const int warpM = warp & 1;    // 0..1
    const int warpN = warp >> 1;   // 0..3
    const int m0 = blockIdx.y * 128;
    const int n0 = blockIdx.x * 128;

    float acc[4][4][4];
    #pragma unroll
    for (int i = 0; i < 4; i++)
        #pragma unroll
        for (int j = 0; j < 4; j++)
            #pragma unroll
            for (int r = 0; r < 4; r++) acc[i][j][r] = 0.f;

    for (int k0 = 0; k0 < K; k0 += 32) {
        // stage tiles (cvt.rna to tf32 at staging time)
        #pragma unroll
        for (int i = 0; i < 4; i++) {
            int v = t + i * 256;        // 0..1023
            int r = v >> 3;             // 0..127
            int c = (v & 7) * 4;        // 0..28
            float4 fa = *(const float4*)&A[(size_t)(m0 + r) * K + k0 + c];
            As[r][c + 0] = f2tf(fa.x); As[r][c + 1] = f2tf(fa.y);
            As[r][c + 2] = f2tf(fa.z); As[r][c + 3] = f2tf(fa.w);
            float4 fw = *(const float4*)&W[(size_t)(n0 + r) * K + k0 + c];
            Ws[r][c + 0] = f2tf(fw.x); Ws[r][c + 1] = f2tf(fw.y);
            Ws[r][c + 2] = f2tf(fw.z); Ws[r][c + 3] = f2tf(fw.w);
        }
        __syncthreads();

        #pragma unroll
        for (int ks = 0; ks < 4; ks++) {
            uint32_t a[4][4], b[4][2];
            #pragma unroll
            for (int mt = 0; mt < 4; mt++) {
                int row = warpM * 64 + mt * 16;
                a[mt][0] = As[row + g    ][ks * 8 + tig    ];
                a[mt][1] = As[row + g + 8][ks * 8 + tig    ];
                a[mt][2] = As[row + g    ][ks * 8 + tig + 4];
                a[mt][3] = As[row + g + 8][ks * 8 + tig + 4];
            }
            #pragma unroll
            for (int nt = 0; nt < 4; nt++) {
                int col = warpN * 32 + nt * 8;
                b[nt][0] = Ws[col + g][ks * 8 + tig    ];
                b[nt][1] = Ws[col + g][ks * 8 + tig + 4];
            }
            #pragma unroll
            for (int mt = 0; mt < 4; mt++)
                #pragma unroll
                for (int nt = 0; nt < 4; nt++)
                    mma_tf32(acc[mt][nt], a[mt], b[nt], acc[mt][nt]);
        }
        __syncthreads();
    }

    // epilogue + bias
    #pragma unroll
    for (int mt = 0; mt < 4; mt++) {
        int rlo = m0 + warpM * 64 + mt * 16 + g;
        #pragma unroll
        for (int nt = 0; nt < 4; nt++) {
            int col = n0 + warpN * 32 + nt * 8 + tig * 2;
            float b0 = bias[col], b1 = bias[col + 1];
            float2 lo = make_float2(acc[mt][nt][0] + b0, acc[mt][nt][1] + b1);
            float2 hi = make_float2(acc[mt][nt][2] + b0, acc[mt][nt][3] + b1);
            *(float2*)&C[(size_t)rlo * N + col]       = lo;
            *(float2*)&C[(size_t)(rlo + 8) * N + col] = hi;
        }
    }
}

// ---------------------------------------------------------------------------
// Fused scores + row stats.  One block = 64 q-rows x full 2048 k-cols strip.
// Writes raw scaled scores into attn, and per-row (max, sumexp) into g_m/g_l
// via online softmax accumulation.  grid: (S/64, B*H), 256 threads.
// Warps: 4 M x 2 N; warp tile 16 rows x 32 cols (4 n-tiles of m16n8).
// ---------------------------------------------------------------------------
__global__ void scores_stats_tf32(const float* __restrict__ Q,
                                  const float* __restrict__ Kp,
                                  float* __restrict__ attn) {
    __shared__ uint32_t Qs[64][68];
    __shared__ uint32_t Ks[64][68];
    __shared__ float red_m[2][64];
    __shared__ float red_l[2][64];

    const int t     = threadIdx.x;
    const int lane  = t & 31;
    const int warp  = t >> 5;
    const int g     = lane >> 2;
    const int tig   = lane & 3;
    const int warpM = warp & 3;    // 0..3
    const int warpN = warp >> 2;   // 0..1
    const int bh = blockIdx.y;
    const int b  = bh >> 4;
    const int h  = bh & 15;
    const int q0 = blockIdx.x * 64;

    // stage Q tile (64 x 64)
    #pragma unroll
    for (int i = 0; i < 4; i++) {
        int v = t + i * 256;
        int r = v >> 4;
        int c = (v & 15) * 4;
        float4 f = *(const float4*)&Q[(size_t)(b * Sc + q0 + r) * Dc + h * DKc + c];
        Qs[r][c + 0] = f2tf(f.x); Qs[r][c + 1] = f2tf(f.y);
        Qs[r][c + 2] = f2tf(f.z); Qs[r][c + 3] = f2tf(f.w);
    }

    float m_lo = -1e30f, m_hi = -1e30f, l_lo = 0.f, l_hi = 0.f;

    for (int kk = 0; kk < Sc; kk += 64) {
        // stage K tile (64 keys x 64 dk)
        #pragma unroll
        for (int i = 0; i < 4; i++) {
            int v = t + i * 256;
            int r = v >> 4;
            int c = (v & 15) * 4;
            float4 f = *(const float4*)&Kp[(size_t)(b * Sc + kk + r) * Dc + h * DKc + c];
            Ks[r][c + 0] = f2tf(f.x); Ks[r][c + 1] = f2tf(f.y);
            Ks[r][c + 2] = f2tf(f.z); Ks[r][c + 3] = f2tf(f.w);
        }
        __syncthreads();

        float acc[4][4];
        #pragma unroll
        for (int nt = 0; nt < 4; nt++)
            #pragma unroll
            for (int r = 0; r < 4; r++) acc[nt][r] = 0.f;

        #pragma unroll
        for (int ks = 0; ks < 8; ks++) {
            uint32_t a[4], bfr[4][2];
            int row = warpM * 16;
            a[0] = Qs[row + g    ][ks * 8 + tig    ];
            a[1] = Qs[row + g + 8][ks * 8 + tig    ];
            a[2] = Qs[row + g    ][ks * 8 + tig + 4];
            a[3] = Qs[row + g + 8][ks * 8 + tig + 4];
            #pragma unroll
            for (int nt = 0; nt < 4; nt++) {
                int key = warpN * 32 + nt * 8 + g;
                bfr[nt][0] = Ks[key][ks * 8 + tig    ];
                bfr[nt][1] = Ks[key][ks * 8 + tig + 4];
            }
            #pragma unroll
            for (int nt = 0; nt < 4; nt++)
                mma_tf32(acc[nt], a, bfr[nt], acc[nt]);
        }

        // scale, write raw scores, online (m,l) update
        const int row = q0 + warpM * 16 + g;
        #pragma unroll
        for (int nt = 0; nt < 4; nt++) {
            float v0 = acc[nt][0] * 0.125f;
            float v1 = acc[nt][1] * 0.125f;
            float v2 = acc[nt][2] * 0.125f;
            float v3 = acc[nt][3] * 0.125f;
            int col = kk + warpN * 32 + nt * 8 + tig * 2;
            *(float2*)&attn[((size_t)bh * Sc + row    ) * Sc + col] = make_float2(v0, v1);
            *(float2*)&attn[((size_t)bh * Sc + row + 8) * Sc + col] = make_float2(v2, v3);

            float nm = fmaxf(m_lo, fmaxf(v0, v1));
            l_lo = l_lo * __expf(m_lo - nm) + __expf(v0 - nm) + __expf(v1 - nm);
            m_lo = nm;
            nm = fmaxf(m_hi, fmaxf(v2, v3));
            l_hi = l_hi * __expf(m_hi - nm) + __expf(v2 - nm) + __expf(v3 - nm);
            m_hi = nm;
        }
        __syncthreads();
    }

    // reduce (m,l) across the 4 lanes of each group
    #pragma unroll
    for (int off = 1; off <= 2; off <<= 1) {
        float mo = __shfl_xor_sync(0xffffffffu, m_lo, off);
        float lo = __shfl_xor_sync(0xffffffffu, l_lo, off);
        float M  = fmaxf(m_lo, mo);
        l_lo = l_lo * __expf(m_lo - M) + lo * __expf(mo - M);
        m_lo = M;
        mo = __shfl_xor_sync(0xffffffffu, m_hi, off);
        lo = __shfl_xor_sync(0xffffffffu, l_hi, off);
        M  = fmaxf(m_hi, mo);
        l_hi = l_hi * __expf(m_hi - M) + lo * __expf(mo - M);
        m_hi = M;
    }
    if (tig == 0) {
        red_m[warpN][warpM * 16 + g]     = m_lo;
        red_l[warpN][warpM * 16 + g]     = l_lo;
        red_m[warpN][warpM * 16 + g + 8] = m_hi;
        red_l[warpN][warpM * 16 + g + 8] = l_hi;
    }
    __syncthreads();
    if (t < 64) {
        float m1 = red_m[0][t], m2 = red_m[1][t];
        float M  = fmaxf(m1, m2);
        float L  = red_l[0][t] * __expf(m1 - M) + red_l[1][t] * __expf(m2 - M);
        g_m[(size_t)bh * Sc + q0 + t] = M;
        g_l[(size_t)bh * Sc + q0 + t] = L;
    }
}

// ---------------------------------------------------------------------------
// Normalize attn in place + ctx = attn @ V (tf32 MMA).
// grid: (S/64, B*H), 256 threads.  Warps: 4 M x 2 N; warp tile 16 q x 32 dk.
// ---------------------------------------------------------------------------
__global__ void av_tf32(float* __restrict__ attn,
                        const float* __restrict__ V,
                        float* __restrict__ ctx) {
    __shared__ uint32_t Ps[64][68];
    __shared__ uint32_t Vs[64][68];
    __shared__ float mrow[64];
    __shared__ float lrow[64];

    const int t     = threadIdx.x;
    const int lane  = t & 31;
    const int warp  = t >> 5;
    const int g     = lane >> 2;
    const int tig   = lane & 3;
    const int warpM = warp & 3;
    const int warpN = warp >> 2;
    const int bh = blockIdx.y;
    const int b  = bh >> 4;
    const int h  = bh & 15;
    const int q0 = blockIdx.x * 64;

    if (t < 64) {
        mrow[t] = g_m[(size_t)bh * Sc + q0 + t];
        lrow[t] = 1.0f / g_l[(size_t)bh * Sc + q0 + t];
    }
    __syncthreads();

    float acc[4][4];
    #pragma unroll
    for (int nt = 0; nt < 4; nt++)
        #pragma unroll
        for (int r = 0; r < 4; r++) acc[nt][r] = 0.f;

    for (int kk = 0; kk < Sc; kk += 64) {
        // stage P tile: read raw scores, exp-normalize, write back, stage tf32
        #pragma unroll
        for (int i = 0; i < 4; i++) {
            int v = t + i * 256;
            int r = v >> 4;
            int c = (v & 15) * 4;
            size_t a = ((size_t)bh * Sc + q0 + r) * Sc + kk + c;
            float4 f = *(float4*)&attn[a];
            float mm = mrow[r], li = lrow[r];
            f.x = __expf(f.x - mm) * li;
            f.y = __expf(f.y - mm) * li;
            f.z = __expf(f.z - mm) * li;
            f.w = __expf(f.w - mm) * li;
            *(float4*)&attn[a] = f;
            Ps[r][c + 0] = f2tf(f.x); Ps[r][c + 1] = f2tf(f.y);
            Ps[r][c + 2] = f2tf(f.z); Ps[r][c + 3] = f2tf(f.w);
        }
        // stage V tile (64 seq x 64 dk)
        #pragma unroll
        for (int i = 0; i < 4; i++) {
            int v = t + i * 256;
            int r = v >> 4;
            int c = (v & 15) * 4;
            float4 f = *(const float4*)&V[(size_t)(b * Sc + kk + r) * Dc + h * DKc + c];
            Vs[r][c + 0] = f2tf(f.x); Vs[r][c + 1] = f2tf(f.y);
            Vs[r][c + 2] = f2tf(f.z); Vs[r][c + 3] = f2tf(f.w);
        }
        __syncthreads();

        #pragma unroll
        for (int ks = 0; ks < 8; ks++) {
            uint32_t a[4], bfr[4][2];
            int row = warpM * 16;
            a[0] = Ps[row + g    ][ks * 8 + tig    ];
            a[1] = Ps[row + g + 8][ks * 8 + tig    ];
            a[2] = Ps[row + g    ][ks * 8 + tig + 4];
            a[3] = Ps[row + g + 8][ks * 8 + tig + 4];
            #pragma unroll
            for (int nt = 0; nt < 4; nt++) {
                int col = warpN * 32 + nt * 8 + g;
                bfr[nt][0] = Vs[ks * 8 + tig    ][col];
                bfr[nt][1] = Vs[ks * 8 + tig + 4][col];
            }
            #pragma unroll
            for (int nt = 0; nt < 4; nt++)
                mma_tf32(acc[nt], a, bfr[nt], acc[nt]);
        }
        __syncthreads();
    }

    // epilogue
    const int rlo = q0 + warpM * 16 + g;
    #pragma unroll
    for (int nt = 0; nt < 4; nt++) {
        int col = warpN * 32 + nt * 8 + tig * 2;
        *(float2*)&ctx[(size_t)(b * Sc + rlo    ) * Dc + h * DKc + col] =
            make_float2(acc[nt][0], acc[nt][1]);
        *(float2*)&ctx[(size_t)(b * Sc + rlo + 8) * Dc + h * DKc + col] =
            make_float2(acc[nt][2], acc[nt][3]);
    }
}

// ---------------------------------------------------------------------------
extern "C" void kernel_launch(void* const* d_in, const int* in_sizes, int n_in,
                              void* d_out, int out_size) {
    const float* x  = (const float*)d_in[0];
    const float* Wq = (const float*)d_in[1];
    const float* bq = (const float*)d_in[2];
    const float* Wk = (const float*)d_in[3];
    const float* bk = (const float*)d_in[4];
    const float* Wv = (const float*)d_in[5];
    const float* bv = (const float*)d_in[6];
    const float* Wo = (const float*)d_in[7];
    const float* bo = (const float*)d_in[8];

    float* out  = (float*)d_out;                       // [B,S,D]
    float* attn = out + (size_t)BSc * Dc;              // [B,H,S,S]

    float *q, *k, *v, *ctx;
    cudaGetSymbolAddress((void**)&q,   g_q);
    cudaGetSymbolAddress((void**)&k,   g_k);
    cudaGetSymbolAddress((void**)&v,   g_v);
    cudaGetSymbolAddress((void**)&ctx, g_ctx);

    dim3 gproj(Dc / 128, BSc / 128);                   // (8, 32)
    gemm_tf32<<<gproj, 256>>>(x, Wq, bq, q, BSc, Dc, Dc);
    gemm_tf32<<<gproj, 256>>>(x, Wk, bk, k, BSc, Dc, Dc);
    gemm_tf32<<<gproj, 256>>>(x, Wv, bv, v, BSc, Dc, Dc);

    dim3 gsc(Sc / 64, BHc);                            // (32, 32)
    scores_stats_tf32<<<gsc, 256>>>(q, k, attn);

    dim3 gav(Sc / 64, BHc);                            // (32, 32)
    av_tf32<<<gav, 256>>>(attn, v, ctx);

    gemm_tf32<<<gproj, 256>>>(ctx, Wo, bo, out, BSc, Dc, Dc);
}